// round 3
// baseline (speedup 1.0000x reference)
#include <cuda_runtime.h>

static constexpr int B_ = 8, C_ = 192, H_ = 128, W_ = 128;
static constexpr int WS_ = 8, SHIFT_ = 4, HD_ = 48;
static constexpr int NW_ = 256;                 // windows per image
static constexpr int T_ = B_ * NW_ * 64;        // 131072 tokens
static constexpr int HID_ = 768;
static constexpr int NPOS_ = 225;

// -------- scratch (device globals; no allocation) --------
__device__ float g_xw[(size_t)T_ * C_];
__device__ float g_xn[(size_t)T_ * C_];
__device__ float g_qkv[(size_t)T_ * 3 * C_];
__device__ float g_att[(size_t)T_ * C_];
__device__ float g_x1[(size_t)T_ * C_];
__device__ float g_hid[(size_t)T_ * HID_];
__device__ float g_x2[(size_t)T_ * C_];

// ============================================================
// helpers: tf32 conversion + m16n8k8 tf32 mma
// ============================================================
__device__ __forceinline__ unsigned f2tf32(float x) {
    unsigned r;
    asm("cvt.rna.tf32.f32 %0, %1;" : "=r"(r) : "f"(x));
    return r;
}

__device__ __forceinline__ void mma_tf32(float* d, const unsigned* a, const unsigned* b) {
    asm volatile(
        "mma.sync.aligned.m16n8k8.row.col.f32.tf32.tf32.f32 "
        "{%0,%1,%2,%3}, {%4,%5,%6,%7}, {%8,%9}, {%0,%1,%2,%3};\n"
        : "+f"(d[0]), "+f"(d[1]), "+f"(d[2]), "+f"(d[3])
        : "r"(a[0]), "r"(a[1]), "r"(a[2]), "r"(a[3]), "r"(b[0]), "r"(b[1]));
}

// ============================================================
// K1: cyclic shift + window partition + LayerNorm1
// ============================================================
__global__ void __launch_bounds__(256) k_part_ln(
    const float* __restrict__ x, const float* __restrict__ gam,
    const float* __restrict__ bet)
{
    __shared__ float s[32 * 193];
    int blk = blockIdx.x;
    int bn = blk >> 1;
    int half = blk & 1;
    int b_i = bn >> 8;
    int n = bn & 255;
    int wh = n >> 4, ww = n & 15;
    int l0 = half * 32;
    const float* xb = x + (size_t)b_i * C_ * H_ * W_;

    for (int idx = threadIdx.x; idx < 32 * C_; idx += 256) {
        int c = idx >> 5;
        int ll = idx & 31;
        int l = l0 + ll;
        int i = l >> 3, j = l & 7;
        int h = (wh * 8 + i + SHIFT_) & (H_ - 1);
        int w = (ww * 8 + j + SHIFT_) & (W_ - 1);
        s[ll * 193 + c] = xb[((size_t)c * H_ + h) * W_ + w];
    }
    __syncthreads();

    int warp = threadIdx.x >> 5, lane = threadIdx.x & 31;
    for (int ll = warp; ll < 32; ll += 8) {
        float v[6];
        float sum = 0.f;
#pragma unroll
        for (int r = 0; r < 6; r++) { v[r] = s[ll * 193 + lane + r * 32]; sum += v[r]; }
#pragma unroll
        for (int o = 16; o; o >>= 1) sum += __shfl_xor_sync(0xffffffffu, sum, o);
        float mu = sum * (1.f / 192.f);
        float var = 0.f;
#pragma unroll
        for (int r = 0; r < 6; r++) { float d = v[r] - mu; var += d * d; }
#pragma unroll
        for (int o = 16; o; o >>= 1) var += __shfl_xor_sync(0xffffffffu, var, o);
        float rs = rsqrtf(var * (1.f / 192.f) + 1e-5f);
        size_t base = ((size_t)bn * 64 + l0 + ll) * C_;
#pragma unroll
        for (int r = 0; r < 6; r++) {
            int c = lane + r * 32;
            g_xw[base + c] = v[r];
            g_xn[base + c] = (v[r] - mu) * rs * gam[c] + bet[c];
        }
    }
}

// ============================================================
// Tensor-core GEMM (tf32 split, fp32-class accuracy):
// C = A(MxK) @ B(KxN) + bias [+R] [gelu]
// BM=128 BN=64 BK=16, 256 threads (4x2 warps, 32x32 each)
// MODE 0: bias; 1: bias+residual; 2: bias+exact GELU
// ============================================================
template <int MODE>
__global__ void __launch_bounds__(256) k_gemm_tc(
    const float* __restrict__ A, const float* __restrict__ Bm,
    const float* __restrict__ bias, const float* __restrict__ R,
    float* __restrict__ Cm, int M, int N, int K)
{
    __shared__ float As[128 * 20];   // [m][k], stride 20 (conflict-free)
    __shared__ float Bs[16 * 72];    // [k][n], stride 72 (conflict-free)

    int tid = threadIdx.x;
    int wid = tid >> 5;
    int lane = tid & 31;
    int wm = wid & 3;           // warp row (4 x 32 = 128)
    int wn = wid >> 2;          // warp col (2 x 32 = 64)
    int m0 = blockIdx.y * 128;
    int n0 = blockIdx.x * 64;
    int lq = lane >> 2;         // 0..7
    int lr = lane & 3;          // 0..3

    float acc[2][4][4];
#pragma unroll
    for (int mt = 0; mt < 2; mt++)
#pragma unroll
        for (int nt = 0; nt < 4; nt++)
#pragma unroll
            for (int e = 0; e < 4; e++) acc[mt][nt][e] = 0.f;

    // G2S index plan
    int ar = tid >> 2;          // 0..63 (two passes: ar, ar+64)
    int ac = (tid & 3) << 2;    // 0,4,8,12
    int bk = tid >> 4;          // 0..15
    int bn4 = (tid & 15) << 2;  // 0..60

    for (int k0 = 0; k0 < K; k0 += 16) {
        float4 a0 = *(const float4*)(A + (size_t)(m0 + ar) * K + k0 + ac);
        float4 a1 = *(const float4*)(A + (size_t)(m0 + ar + 64) * K + k0 + ac);
        float4 bv = *(const float4*)(Bm + (size_t)(k0 + bk) * N + n0 + bn4);
        __syncthreads();   // protect previous iteration's reads
        *(float4*)(&As[ar * 20 + ac]) = a0;
        *(float4*)(&As[(ar + 64) * 20 + ac]) = a1;
        *(float4*)(&Bs[bk * 72 + bn4]) = bv;
        __syncthreads();

#pragma unroll
        for (int ks = 0; ks < 16; ks += 8) {
            // A fragments (fp32 from smem, split to tf32 big+res)
            unsigned ab[2][4], ar_[2][4];
#pragma unroll
            for (int mt = 0; mt < 2; mt++) {
                int mrow = wm * 32 + mt * 16 + lq;
                float f0 = As[mrow * 20 + ks + lr];
                float f1 = As[(mrow + 8) * 20 + ks + lr];
                float f2 = As[mrow * 20 + ks + lr + 4];
                float f3 = As[(mrow + 8) * 20 + ks + lr + 4];
                ab[mt][0] = f2tf32(f0); ar_[mt][0] = f2tf32(f0 - __uint_as_float(ab[mt][0]));
                ab[mt][1] = f2tf32(f1); ar_[mt][1] = f2tf32(f1 - __uint_as_float(ab[mt][1]));
                ab[mt][2] = f2tf32(f2); ar_[mt][2] = f2tf32(f2 - __uint_as_float(ab[mt][2]));
                ab[mt][3] = f2tf32(f3); ar_[mt][3] = f2tf32(f3 - __uint_as_float(ab[mt][3]));
            }
            // B fragments
            unsigned bb[4][2], br[4][2];
#pragma unroll
            for (int nt = 0; nt < 4; nt++) {
                int ncol = wn * 32 + nt * 8 + lq;
                float f0 = Bs[(ks + lr) * 72 + ncol];
                float f1 = Bs[(ks + lr + 4) * 72 + ncol];
                bb[nt][0] = f2tf32(f0); br[nt][0] = f2tf32(f0 - __uint_as_float(bb[nt][0]));
                bb[nt][1] = f2tf32(f1); br[nt][1] = f2tf32(f1 - __uint_as_float(bb[nt][1]));
            }
#pragma unroll
            for (int mt = 0; mt < 2; mt++)
#pragma unroll
                for (int nt = 0; nt < 4; nt++) {
                    mma_tf32(acc[mt][nt], ab[mt], bb[nt]);
                    mma_tf32(acc[mt][nt], ab[mt], br[nt]);
                    mma_tf32(acc[mt][nt], ar_[mt], bb[nt]);
                }
        }
    }

    // epilogue: c0,c1 at (row, 2*lr), c2,c3 at (row+8, 2*lr)
#pragma unroll
    for (int mt = 0; mt < 2; mt++) {
#pragma unroll
        for (int nt = 0; nt < 4; nt++) {
            int ncol = wn * 32 + nt * 8 + 2 * lr;
            float bx = bias[n0 + ncol], by = bias[n0 + ncol + 1];
#pragma unroll
            for (int half = 0; half < 2; half++) {
                size_t row = (size_t)m0 + wm * 32 + mt * 16 + lq + half * 8;
                float v0 = acc[mt][nt][half * 2 + 0] + bx;
                float v1 = acc[mt][nt][half * 2 + 1] + by;
                if (MODE == 1) {
                    float2 rr = *(const float2*)(R + row * N + n0 + ncol);
                    v0 += rr.x; v1 += rr.y;
                }
                if (MODE == 2) {
                    v0 = 0.5f * v0 * (1.f + erff(v0 * 0.70710678118654752f));
                    v1 = 0.5f * v1 * (1.f + erff(v1 * 0.70710678118654752f));
                }
                *(float2*)(Cm + row * N + n0 + ncol) = make_float2(v0, v1);
            }
        }
    }
}

// ============================================================
// K3: windowed attention, one block per (window, head)
// ============================================================
__global__ void __launch_bounds__(256) k_attn(const float* __restrict__ rbt)
{
    __shared__ float qv[64 * 49];   // q, later reused for v
    __shared__ float kb[64 * 49];
    __shared__ float sc[64 * 64];
    __shared__ float sb[NPOS_];
    __shared__ int rid[64];

    int bid = blockIdx.x;
    int head = bid & 3;
    int bn = bid >> 2;
    int n = bn & 255;
    int wh = n >> 4, ww = n & 15;
    int tid = threadIdx.x;
    size_t qbase = (size_t)bn * 64 * 576 + head * 48;

    for (int idx = tid; idx < 64 * 48; idx += 256) {
        int l = idx / 48, d = idx - l * 48;
        qv[l * 49 + d] = g_qkv[qbase + (size_t)l * 576 + d];
        kb[l * 49 + d] = g_qkv[qbase + (size_t)l * 576 + 192 + d];
    }
    for (int idx = tid; idx < NPOS_; idx += 256) sb[idx] = rbt[head * NPOS_ + idx];
    if (tid < 64) {
        int i = tid >> 3, j = tid & 7;
        int h = wh * 8 + i, w = ww * 8 + j;
        int rh = (h < 120) ? 0 : ((h < 124) ? 1 : 2);
        int rw = (w < 120) ? 0 : ((w < 124) ? 1 : 2);
        rid[tid] = rh * 3 + rw;
    }
    __syncthreads();

    {
        int j = tid & 63;
        float kreg[48];
#pragma unroll
        for (int d = 0; d < 48; d++) kreg[d] = kb[j * 49 + d];
        int yj = j >> 3, xj = j & 7;
        int rj = rid[j];
        const float scale = 0.14433756729740643f;  // 1/sqrt(48)
        for (int i = tid >> 6; i < 64; i += 4) {
            float dot = 0.f;
#pragma unroll
            for (int d = 0; d < 48; d++) dot += qv[i * 49 + d] * kreg[d];
            int yi = i >> 3, xi = i & 7;
            float bias_v = (rid[i] != rj) ? -100.f
                         : sb[(yi - yj + 7) * 15 + (xi - xj + 7)];
            sc[i * 64 + j] = dot * scale + bias_v;
        }
    }
    __syncthreads();

    for (int idx = tid; idx < 64 * 48; idx += 256) {
        int l = idx / 48, d = idx - l * 48;
        qv[l * 49 + d] = g_qkv[qbase + (size_t)l * 576 + 384 + d];
    }
    {
        int warp = tid >> 5, lane = tid & 31;
        for (int row = warp; row < 64; row += 8) {
            float a = sc[row * 64 + lane], b2 = sc[row * 64 + lane + 32];
            float m = fmaxf(a, b2);
#pragma unroll
            for (int o = 16; o; o >>= 1) m = fmaxf(m, __shfl_xor_sync(0xffffffffu, m, o));
            float ea = __expf(a - m), eb = __expf(b2 - m);
            float sum = ea + eb;
#pragma unroll
            for (int o = 16; o; o >>= 1) sum += __shfl_xor_sync(0xffffffffu, sum, o);
            float inv = 1.f / sum;
            sc[row * 64 + lane] = ea * inv;
            sc[row * 64 + lane + 32] = eb * inv;
        }
    }
    __syncthreads();

    size_t obase = (size_t)bn * 64 * 192 + head * 48;
    for (int e = tid; e < 64 * 48; e += 256) {
        int i = e / 48, d = e - i * 48;
        float acc = 0.f;
#pragma unroll
        for (int j = 0; j < 64; j++) acc += sc[i * 64 + j] * qv[j * 49 + d];
        g_att[obase + (size_t)i * 192 + d] = acc;
    }
}

// ============================================================
// K5: plain LayerNorm over C=192, warp per token
// ============================================================
__global__ void __launch_bounds__(256) k_ln(
    const float* __restrict__ in, const float* __restrict__ gam,
    const float* __restrict__ bet, float* __restrict__ out)
{
    int warp = threadIdx.x >> 5, lane = threadIdx.x & 31;
    size_t t = (size_t)blockIdx.x * 8 + warp;
    const float* p = in + t * C_;
    float v[6];
    float sum = 0.f;
#pragma unroll
    for (int r = 0; r < 6; r++) { v[r] = p[lane + r * 32]; sum += v[r]; }
#pragma unroll
    for (int o = 16; o; o >>= 1) sum += __shfl_xor_sync(0xffffffffu, sum, o);
    float mu = sum * (1.f / 192.f);
    float var = 0.f;
#pragma unroll
    for (int r = 0; r < 6; r++) { float d = v[r] - mu; var += d * d; }
#pragma unroll
    for (int o = 16; o; o >>= 1) var += __shfl_xor_sync(0xffffffffu, var, o);
    float rs = rsqrtf(var * (1.f / 192.f) + 1e-5f);
#pragma unroll
    for (int r = 0; r < 6; r++) {
        int c = lane + r * 32;
        out[t * C_ + c] = (v[r] - mu) * rs * gam[c] + bet[c];
    }
}

// ============================================================
// K8: window reverse + roll-back into (B,C,H,W)
// ============================================================
__global__ void __launch_bounds__(256) k_unpart(float* __restrict__ out)
{
    __shared__ float s[32 * 193];
    int blk = blockIdx.x;
    int bn = blk >> 1, half = blk & 1;
    int b_i = bn >> 8, n = bn & 255;
    int wh = n >> 4, ww = n & 15;
    int l0 = half * 32;
    size_t tbase = ((size_t)bn * 64 + l0) * C_;

    for (int idx = threadIdx.x; idx < 32 * C_; idx += 256) {
        int ll = idx / 192, c = idx - ll * 192;
        s[ll * 193 + c] = g_x2[tbase + (size_t)ll * 192 + c];
    }
    __syncthreads();
    float* ob = out + (size_t)b_i * C_ * H_ * W_;
    for (int idx = threadIdx.x; idx < 32 * C_; idx += 256) {
        int c = idx >> 5, ll = idx & 31;
        int l = l0 + ll;
        int i = l >> 3, j = l & 7;
        int h = (wh * 8 + i + SHIFT_) & (H_ - 1);
        int w = (ww * 8 + j + SHIFT_) & (W_ - 1);
        ob[((size_t)c * H_ + h) * W_ + w] = s[ll * 193 + c];
    }
}

// ============================================================
extern "C" void kernel_launch(void* const* d_in, const int* in_sizes, int n_in,
                              void* d_out, int out_size)
{
    const float* x      = (const float*)d_in[0];
    const float* rbt    = (const float*)d_in[1];
    const float* qkv_w  = (const float*)d_in[2];
    const float* qkv_b  = (const float*)d_in[3];
    const float* proj_w = (const float*)d_in[4];
    const float* proj_b = (const float*)d_in[5];
    const float* n1g    = (const float*)d_in[6];
    const float* n1b    = (const float*)d_in[7];
    const float* n2g    = (const float*)d_in[8];
    const float* n2b    = (const float*)d_in[9];
    const float* w1     = (const float*)d_in[10];
    const float* b1     = (const float*)d_in[11];
    const float* w2     = (const float*)d_in[12];
    const float* b2     = (const float*)d_in[13];
    float* out = (float*)d_out;

    float *p_xw, *p_xn, *p_qkv, *p_att, *p_x1, *p_hid, *p_x2;
    cudaGetSymbolAddress((void**)&p_xw,  g_xw);
    cudaGetSymbolAddress((void**)&p_xn,  g_xn);
    cudaGetSymbolAddress((void**)&p_qkv, g_qkv);
    cudaGetSymbolAddress((void**)&p_att, g_att);
    cudaGetSymbolAddress((void**)&p_x1,  g_x1);
    cudaGetSymbolAddress((void**)&p_hid, g_hid);
    cudaGetSymbolAddress((void**)&p_x2,  g_x2);

    // 1. shift + partition + LN1  -> g_xw (shortcut), g_xn
    k_part_ln<<<4096, 256>>>(x, n1g, n1b);
    // 2. QKV GEMM: (T,192) @ (192,576)
    k_gemm_tc<0><<<dim3(9, T_ / 128), 256>>>(p_xn, qkv_w, qkv_b, nullptr, p_qkv, T_, 576, 192);
    // 3. windowed attention -> g_att
    k_attn<<<8192, 256>>>(rbt);
    // 4. proj GEMM + residual: x1 = xw + att @ proj_w + b
    k_gemm_tc<1><<<dim3(3, T_ / 128), 256>>>(p_att, proj_w, proj_b, p_xw, p_x1, T_, 192, 192);
    // 5. LN2 -> g_xn (reuse)
    k_ln<<<T_ / 8, 256>>>(p_x1, n2g, n2b, p_xn);
    // 6. MLP1 GEMM + GELU: (T,192)@(192,768)
    k_gemm_tc<2><<<dim3(12, T_ / 128), 256>>>(p_xn, w1, b1, nullptr, p_hid, T_, 768, 192);
    // 7. MLP2 GEMM + residual: x2 = x1 + hid @ w2 + b2
    k_gemm_tc<1><<<dim3(3, T_ / 128), 256>>>(p_hid, w2, b2, p_x1, p_x2, T_, 192, 768);
    // 8. window reverse + roll -> out
    k_unpart<<<4096, 256>>>(out);
}

// round 15
// speedup vs baseline: 1.6149x; 1.6149x over previous
#include <cuda_runtime.h>

static constexpr int B_ = 8, C_ = 192, H_ = 128, W_ = 128;
static constexpr int WS_ = 8, SHIFT_ = 4, HD_ = 48;
static constexpr int NW_ = 256;                 // windows per image
static constexpr int T_ = B_ * NW_ * 64;        // 131072 tokens
static constexpr int HID_ = 768;
static constexpr int NPOS_ = 225;
static constexpr int SCS_ = 66;                 // sc row stride (EVEN: float2-aligned)

// -------- scratch (device globals; no allocation) --------
__device__ float g_xw[(size_t)T_ * C_];
__device__ float g_xn[(size_t)T_ * C_];
__device__ float g_qkv[(size_t)T_ * 3 * C_];
__device__ float g_att[(size_t)T_ * C_];
__device__ float g_x1[(size_t)T_ * C_];
__device__ float g_hid[(size_t)T_ * HID_];
__device__ float g_x2[(size_t)T_ * C_];

// packed bf16x2 split weights: [n][K/2] u32, hi/lo
static constexpr int WOFF_QKV = 0, WOFF_PROJ = 55296, WOFF_W1 = 73728, WOFF_W2 = 147456;
__device__ unsigned g_wh[221184];
__device__ unsigned g_wl[221184];

// ============================================================
// helpers
// ============================================================
__device__ __forceinline__ void split2(float f0, float f1, unsigned& hi, unsigned& lo) {
    unsigned u0 = __float_as_uint(f0), u1 = __float_as_uint(f1);
    hi = __byte_perm(u0, u1, 0x7632);          // {hi16(f1), hi16(f0)}
    float r0 = f0 - __uint_as_float(u0 & 0xFFFF0000u);
    float r1 = f1 - __uint_as_float(u1 & 0xFFFF0000u);
    asm("cvt.rn.bf16x2.f32 %0, %1, %2;" : "=r"(lo) : "f"(r1), "f"(r0));
}

__device__ __forceinline__ void mma_bf16(float* d, const unsigned* a, const unsigned* b) {
    asm volatile(
        "mma.sync.aligned.m16n8k16.row.col.f32.bf16.bf16.f32 "
        "{%0,%1,%2,%3}, {%4,%5,%6,%7}, {%8,%9}, {%0,%1,%2,%3};\n"
        : "+f"(d[0]), "+f"(d[1]), "+f"(d[2]), "+f"(d[3])
        : "r"(a[0]), "r"(a[1]), "r"(a[2]), "r"(a[3]), "r"(b[0]), "r"(b[1]));
}

// ============================================================
// K0: weight pre-split. W is [K][N] fp32 -> hi/lo packed [n][K/2]
// ============================================================
__global__ void __launch_bounds__(256) k_wsplit(
    const float* __restrict__ W, unsigned* __restrict__ hi,
    unsigned* __restrict__ lo, int K, int N)
{
    int i = blockIdx.x * 256 + threadIdx.x;
    int kp2 = K >> 1;
    if (i >= N * kp2) return;
    int n = i / kp2, kp = i - n * kp2;
    float f0 = W[(size_t)(2 * kp) * N + n];
    float f1 = W[(size_t)(2 * kp + 1) * N + n];
    unsigned h, l;
    split2(f0, f1, h, l);
    hi[i] = h;
    lo[i] = l;
}

// ============================================================
// K1: cyclic shift + window partition + LayerNorm1
// ============================================================
__global__ void __launch_bounds__(256) k_part_ln(
    const float* __restrict__ x, const float* __restrict__ gam,
    const float* __restrict__ bet)
{
    __shared__ __align__(16) float s[32 * 193];
    int blk = blockIdx.x;
    int bn = blk >> 1;
    int half = blk & 1;
    int b_i = bn >> 8;
    int n = bn & 255;
    int wh = n >> 4, ww = n & 15;
    int l0 = half * 32;
    const float* xb = x + (size_t)b_i * C_ * H_ * W_;

    for (int idx = threadIdx.x; idx < 32 * C_; idx += 256) {
        int c = idx >> 5;
        int ll = idx & 31;
        int l = l0 + ll;
        int i = l >> 3, j = l & 7;
        int h = (wh * 8 + i + SHIFT_) & (H_ - 1);
        int w = (ww * 8 + j + SHIFT_) & (W_ - 1);
        s[ll * 193 + c] = xb[((size_t)c * H_ + h) * W_ + w];
    }
    __syncthreads();

    int warp = threadIdx.x >> 5, lane = threadIdx.x & 31;
    for (int ll = warp; ll < 32; ll += 8) {
        float v[6];
        float sum = 0.f;
#pragma unroll
        for (int r = 0; r < 6; r++) { v[r] = s[ll * 193 + lane + r * 32]; sum += v[r]; }
#pragma unroll
        for (int o = 16; o; o >>= 1) sum += __shfl_xor_sync(0xffffffffu, sum, o);
        float mu = sum * (1.f / 192.f);
        float var = 0.f;
#pragma unroll
        for (int r = 0; r < 6; r++) { float d = v[r] - mu; var += d * d; }
#pragma unroll
        for (int o = 16; o; o >>= 1) var += __shfl_xor_sync(0xffffffffu, var, o);
        float rs = rsqrtf(var * (1.f / 192.f) + 1e-5f);
        size_t base = ((size_t)bn * 64 + l0 + ll) * C_;
#pragma unroll
        for (int r = 0; r < 6; r++) {
            int c = lane + r * 32;
            g_xw[base + c] = v[r];
            g_xn[base + c] = (v[r] - mu) * rs * gam[c] + bet[c];
        }
    }
}

// ============================================================
// Tensor-core GEMM, bf16 3-term split (fp32-class accuracy)
// ============================================================
template <int MODE>
__global__ void __launch_bounds__(256) k_gemm_bf(
    const float* __restrict__ A, const unsigned* __restrict__ Bhi,
    const unsigned* __restrict__ Blo, const float* __restrict__ bias,
    const float* __restrict__ R, float* __restrict__ Cm,
    int M, int N, int K)
{
    __shared__ __align__(16) float As[128 * 40];
    __shared__ __align__(16) unsigned BsH[64 * 20];
    __shared__ __align__(16) unsigned BsL[64 * 20];

    int tid = threadIdx.x;
    int wid = tid >> 5;
    int lane = tid & 31;
    int wm = wid & 3;
    int wn = wid >> 2;
    int m0 = blockIdx.y * 128;
    int n0 = blockIdx.x * 64;
    int lq = lane >> 2;
    int lr = lane & 3;
    int Kp = K >> 1;

    float acc[2][4][4];
#pragma unroll
    for (int mt = 0; mt < 2; mt++)
#pragma unroll
        for (int nt = 0; nt < 4; nt++)
#pragma unroll
            for (int e = 0; e < 4; e++) acc[mt][nt][e] = 0.f;

    int ar_ = tid >> 3;
    int ac4 = (tid & 7) << 2;
    int bn_ = tid >> 2;
    int bc4 = (tid & 3) << 2;

    for (int k0 = 0; k0 < K; k0 += 32) {
        float4 av0 = *(const float4*)(A + (size_t)(m0 + ar_) * K + k0 + ac4);
        float4 av1 = *(const float4*)(A + (size_t)(m0 + ar_ + 32) * K + k0 + ac4);
        float4 av2 = *(const float4*)(A + (size_t)(m0 + ar_ + 64) * K + k0 + ac4);
        float4 av3 = *(const float4*)(A + (size_t)(m0 + ar_ + 96) * K + k0 + ac4);
        uint4 bh4 = *(const uint4*)(Bhi + (size_t)(n0 + bn_) * Kp + (k0 >> 1) + bc4);
        uint4 bl4 = *(const uint4*)(Blo + (size_t)(n0 + bn_) * Kp + (k0 >> 1) + bc4);
        __syncthreads();
        *(float4*)(&As[ar_ * 40 + ac4]) = av0;
        *(float4*)(&As[(ar_ + 32) * 40 + ac4]) = av1;
        *(float4*)(&As[(ar_ + 64) * 40 + ac4]) = av2;
        *(float4*)(&As[(ar_ + 96) * 40 + ac4]) = av3;
        *(uint4*)(&BsH[bn_ * 20 + bc4]) = bh4;
        *(uint4*)(&BsL[bn_ * 20 + bc4]) = bl4;
        __syncthreads();

#pragma unroll
        for (int ks = 0; ks < 32; ks += 16) {
            unsigned ah[2][4], al[2][4];
#pragma unroll
            for (int mt = 0; mt < 2; mt++) {
                int mrow = wm * 32 + mt * 16 + lq;
                float2 p0 = *(const float2*)(&As[mrow * 40 + ks + 2 * lr]);
                float2 p1 = *(const float2*)(&As[(mrow + 8) * 40 + ks + 2 * lr]);
                float2 p2 = *(const float2*)(&As[mrow * 40 + ks + 2 * lr + 8]);
                float2 p3 = *(const float2*)(&As[(mrow + 8) * 40 + ks + 2 * lr + 8]);
                split2(p0.x, p0.y, ah[mt][0], al[mt][0]);
                split2(p1.x, p1.y, ah[mt][1], al[mt][1]);
                split2(p2.x, p2.y, ah[mt][2], al[mt][2]);
                split2(p3.x, p3.y, ah[mt][3], al[mt][3]);
            }
            unsigned bh[4][2], bl[4][2];
#pragma unroll
            for (int nt = 0; nt < 4; nt++) {
                int ncol = wn * 32 + nt * 8 + lq;
                int kp = (ks >> 1) + lr;
                bh[nt][0] = BsH[ncol * 20 + kp];
                bh[nt][1] = BsH[ncol * 20 + kp + 4];
                bl[nt][0] = BsL[ncol * 20 + kp];
                bl[nt][1] = BsL[ncol * 20 + kp + 4];
            }
#pragma unroll
            for (int mt = 0; mt < 2; mt++)
#pragma unroll
                for (int nt = 0; nt < 4; nt++) {
                    mma_bf16(acc[mt][nt], ah[mt], bh[nt]);
                    mma_bf16(acc[mt][nt], ah[mt], bl[nt]);
                    mma_bf16(acc[mt][nt], al[mt], bh[nt]);
                }
        }
    }

#pragma unroll
    for (int mt = 0; mt < 2; mt++) {
#pragma unroll
        for (int nt = 0; nt < 4; nt++) {
            int ncol = wn * 32 + nt * 8 + 2 * lr;
            float bx = bias[n0 + ncol], by = bias[n0 + ncol + 1];
#pragma unroll
            for (int half = 0; half < 2; half++) {
                size_t row = (size_t)m0 + wm * 32 + mt * 16 + lq + half * 8;
                float v0 = acc[mt][nt][half * 2 + 0] + bx;
                float v1 = acc[mt][nt][half * 2 + 1] + by;
                if (MODE == 1) {
                    float2 rr = *(const float2*)(R + row * N + n0 + ncol);
                    v0 += rr.x; v1 += rr.y;
                }
                if (MODE == 2) {
                    v0 = 0.5f * v0 * (1.f + erff(v0 * 0.70710678118654752f));
                    v1 = 0.5f * v1 * (1.f + erff(v1 * 0.70710678118654752f));
                }
                *(float2*)(Cm + row * N + n0 + ncol) = make_float2(v0, v1);
            }
        }
    }
}

// ============================================================
// K3: windowed attention via bf16-split tensor cores
// block = 128 threads (4 warps), one (window, head) per block
// ============================================================
__global__ void __launch_bounds__(128) k_attn_tc(const float* __restrict__ rbt)
{
    // union buffer: phase1 = Qh/Ql/Kh/Kl [64][24] u32, stride 25
    //               phase2 = Vth/Vtl [48][32] u32, stride 33 (V transposed)
    __shared__ __align__(16) unsigned buf[6400];   // 25.6 KB
    __shared__ __align__(16) float sc[64 * SCS_];  // 16.9 KB, EVEN stride
    __shared__ float sb[NPOS_];
    __shared__ int rid[64];

    unsigned* Qh = buf;
    unsigned* Ql = buf + 1600;
    unsigned* Kh = buf + 3200;
    unsigned* Kl = buf + 4800;
    unsigned* Vth = buf;                      // overlays Qh/Ql after phase 1
    unsigned* Vtl = buf + 1584;

    int bid = blockIdx.x;
    int head = bid & 3;
    int bn = bid >> 2;
    int n = bn & 255;
    int wh = n >> 4, ww = n & 15;
    int tid = threadIdx.x;
    int warp = tid >> 5, lane = tid & 31;
    int lq = lane >> 2, lr = lane & 3;
    int m0 = warp * 16;
    size_t qbase = (size_t)bn * 64 * 576 + head * 48;

    // ---- load + split Q, K ----
    for (int idx = tid; idx < 64 * 24; idx += 128) {
        int l = idx / 24, kp = idx - l * 24;
        const float* qp = g_qkv + qbase + (size_t)l * 576 + 2 * kp;
        split2(qp[0], qp[1], Qh[l * 25 + kp], Ql[l * 25 + kp]);
        split2(qp[192], qp[193], Kh[l * 25 + kp], Kl[l * 25 + kp]);
    }
    for (int idx = tid; idx < NPOS_; idx += 128) sb[idx] = rbt[head * NPOS_ + idx];
    if (tid < 64) {
        int i = tid >> 3, j = tid & 7;
        int h = wh * 8 + i, w = ww * 8 + j;
        int rh = (h < 120) ? 0 : ((h < 124) ? 1 : 2);
        int rw = (w < 120) ? 0 : ((w < 124) ? 1 : 2);
        rid[tid] = rh * 3 + rw;
    }
    __syncthreads();

    // ---- phase 1: S = Q K^T ----
    float accS[8][4];
#pragma unroll
    for (int nt = 0; nt < 8; nt++)
#pragma unroll
        for (int e = 0; e < 4; e++) accS[nt][e] = 0.f;

#pragma unroll
    for (int ks = 0; ks < 3; ks++) {
        int kb = 8 * ks;
        unsigned ah[4], al_[4];
        ah[0] = Qh[(m0 + lq) * 25 + kb + lr];
        ah[1] = Qh[(m0 + lq + 8) * 25 + kb + lr];
        ah[2] = Qh[(m0 + lq) * 25 + kb + lr + 4];
        ah[3] = Qh[(m0 + lq + 8) * 25 + kb + lr + 4];
        al_[0] = Ql[(m0 + lq) * 25 + kb + lr];
        al_[1] = Ql[(m0 + lq + 8) * 25 + kb + lr];
        al_[2] = Ql[(m0 + lq) * 25 + kb + lr + 4];
        al_[3] = Ql[(m0 + lq + 8) * 25 + kb + lr + 4];
#pragma unroll
        for (int nt = 0; nt < 8; nt++) {
            int nc = nt * 8 + lq;
            unsigned bh[2] = {Kh[nc * 25 + kb + lr], Kh[nc * 25 + kb + lr + 4]};
            unsigned bl[2] = {Kl[nc * 25 + kb + lr], Kl[nc * 25 + kb + lr + 4]};
            mma_bf16(accS[nt], ah, bh);
            mma_bf16(accS[nt], ah, bl);
            mma_bf16(accS[nt], al_, bh);
        }
    }

    // spill S with scale + relative-position bias + shift mask
    {
        const float scale = 0.14433756729740643f;  // 1/sqrt(48)
        int i0 = m0 + lq, i1 = i0 + 8;
        int yi0 = i0 >> 3, xi0 = i0 & 7;
        int yi1 = i1 >> 3, xi1 = i1 & 7;
        int r0 = rid[i0], r1 = rid[i1];
#pragma unroll
        for (int nt = 0; nt < 8; nt++) {
#pragma unroll
            for (int e = 0; e < 2; e++) {
                int j = nt * 8 + 2 * lr + e;
                int yj = j >> 3, xj = j & 7;
                int rj = rid[j];
                float b0 = (r0 != rj) ? -100.f : sb[(yi0 - yj + 7) * 15 + (xi0 - xj + 7)];
                float b1 = (r1 != rj) ? -100.f : sb[(yi1 - yj + 7) * 15 + (xi1 - xj + 7)];
                sc[i0 * SCS_ + j] = accS[nt][e] * scale + b0;
                sc[i1 * SCS_ + j] = accS[nt][2 + e] * scale + b1;
            }
        }
    }
    __syncthreads();   // S complete; Q/K smem free

    // ---- load V transposed + split (reuses Q/K buffer) ----
    for (int idx = tid; idx < 48 * 32; idx += 128) {
        int jp = idx / 48, d = idx - jp * 48;
        float v0 = g_qkv[qbase + (size_t)(2 * jp) * 576 + 384 + d];
        float v1 = g_qkv[qbase + (size_t)(2 * jp + 1) * 576 + 384 + d];
        split2(v0, v1, Vth[d * 33 + jp], Vtl[d * 33 + jp]);
    }

    // ---- softmax (4 warps, 16 rows each) ----
    for (int row = warp; row < 64; row += 4) {
        float a = sc[row * SCS_ + lane], b2 = sc[row * SCS_ + lane + 32];
        float m = fmaxf(a, b2);
#pragma unroll
        for (int o = 16; o; o >>= 1) m = fmaxf(m, __shfl_xor_sync(0xffffffffu, m, o));
        float ea = __expf(a - m), eb = __expf(b2 - m);
        float sum = ea + eb;
#pragma unroll
        for (int o = 16; o; o >>= 1) sum += __shfl_xor_sync(0xffffffffu, sum, o);
        float inv = 1.f / sum;
        sc[row * SCS_ + lane] = ea * inv;
        sc[row * SCS_ + lane + 32] = eb * inv;
    }
    __syncthreads();

    // ---- phase 2: O = P V ----
    float accO[6][4];
#pragma unroll
    for (int nt = 0; nt < 6; nt++)
#pragma unroll
        for (int e = 0; e < 4; e++) accO[nt][e] = 0.f;

#pragma unroll
    for (int ks = 0; ks < 4; ks++) {
        int k0 = 16 * ks;
        float2 p0 = *(const float2*)(&sc[(m0 + lq) * SCS_ + k0 + 2 * lr]);
        float2 p1 = *(const float2*)(&sc[(m0 + lq + 8) * SCS_ + k0 + 2 * lr]);
        float2 p2 = *(const float2*)(&sc[(m0 + lq) * SCS_ + k0 + 2 * lr + 8]);
        float2 p3 = *(const float2*)(&sc[(m0 + lq + 8) * SCS_ + k0 + 2 * lr + 8]);
        unsigned ah[4], al_[4];
        split2(p0.x, p0.y, ah[0], al_[0]);
        split2(p1.x, p1.y, ah[1], al_[1]);
        split2(p2.x, p2.y, ah[2], al_[2]);
        split2(p3.x, p3.y, ah[3], al_[3]);
        int kb = 8 * ks;
#pragma unroll
        for (int nt = 0; nt < 6; nt++) {
            int dc = nt * 8 + lq;
            unsigned bh[2] = {Vth[dc * 33 + kb + lr], Vth[dc * 33 + kb + lr + 4]};
            unsigned bl[2] = {Vtl[dc * 33 + kb + lr], Vtl[dc * 33 + kb + lr + 4]};
            mma_bf16(accO[nt], ah, bh);
            mma_bf16(accO[nt], ah, bl);
            mma_bf16(accO[nt], al_, bh);
        }
    }

    // ---- write O ----
    size_t obase = (size_t)bn * 64 * 192 + head * 48;
#pragma unroll
    for (int nt = 0; nt < 6; nt++) {
        int d0 = nt * 8 + 2 * lr;
        *(float2*)(&g_att[obase + (size_t)(m0 + lq) * 192 + d0]) =
            make_float2(accO[nt][0], accO[nt][1]);
        *(float2*)(&g_att[obase + (size_t)(m0 + lq + 8) * 192 + d0]) =
            make_float2(accO[nt][2], accO[nt][3]);
    }
}

// ============================================================
// K5: plain LayerNorm over C=192, warp per token
// ============================================================
__global__ void __launch_bounds__(256) k_ln(
    const float* __restrict__ in, const float* __restrict__ gam,
    const float* __restrict__ bet, float* __restrict__ out)
{
    int warp = threadIdx.x >> 5, lane = threadIdx.x & 31;
    size_t t = (size_t)blockIdx.x * 8 + warp;
    const float* p = in + t * C_;
    float v[6];
    float sum = 0.f;
#pragma unroll
    for (int r = 0; r < 6; r++) { v[r] = p[lane + r * 32]; sum += v[r]; }
#pragma unroll
    for (int o = 16; o; o >>= 1) sum += __shfl_xor_sync(0xffffffffu, sum, o);
    float mu = sum * (1.f / 192.f);
    float var = 0.f;
#pragma unroll
    for (int r = 0; r < 6; r++) { float d = v[r] - mu; var += d * d; }
#pragma unroll
    for (int o = 16; o; o >>= 1) var += __shfl_xor_sync(0xffffffffu, var, o);
    float rs = rsqrtf(var * (1.f / 192.f) + 1e-5f);
#pragma unroll
    for (int r = 0; r < 6; r++) {
        int c = lane + r * 32;
        out[t * C_ + c] = (v[r] - mu) * rs * gam[c] + bet[c];
    }
}

// ============================================================
// K8: window reverse + roll-back into (B,C,H,W)
// ============================================================
__global__ void __launch_bounds__(256) k_unpart(float* __restrict__ out)
{
    __shared__ __align__(16) float s[32 * 193];
    int blk = blockIdx.x;
    int bn = blk >> 1, half = blk & 1;
    int b_i = bn >> 8, n = bn & 255;
    int wh = n >> 4, ww = n & 15;
    int l0 = half * 32;
    size_t tbase = ((size_t)bn * 64 + l0) * C_;

    for (int idx = threadIdx.x; idx < 32 * C_; idx += 256) {
        int ll = idx / 192, c = idx - ll * 192;
        s[ll * 193 + c] = g_x2[tbase + (size_t)ll * 192 + c];
    }
    __syncthreads();
    float* ob = out + (size_t)b_i * C_ * H_ * W_;
    for (int idx = threadIdx.x; idx < 32 * C_; idx += 256) {
        int c = idx >> 5, ll = idx & 31;
        int l = l0 + ll;
        int i = l >> 3, j = l & 7;
        int h = (wh * 8 + i + SHIFT_) & (H_ - 1);
        int w = (ww * 8 + j + SHIFT_) & (W_ - 1);
        ob[((size_t)c * H_ + h) * W_ + w] = s[ll * 193 + c];
    }
}

// ============================================================
extern "C" void kernel_launch(void* const* d_in, const int* in_sizes, int n_in,
                              void* d_out, int out_size)
{
    const float* x      = (const float*)d_in[0];
    const float* rbt    = (const float*)d_in[1];
    const float* qkv_w  = (const float*)d_in[2];
    const float* qkv_b  = (const float*)d_in[3];
    const float* proj_w = (const float*)d_in[4];
    const float* proj_b = (const float*)d_in[5];
    const float* n1g    = (const float*)d_in[6];
    const float* n1b    = (const float*)d_in[7];
    const float* n2g    = (const float*)d_in[8];
    const float* n2b    = (const float*)d_in[9];
    const float* w1     = (const float*)d_in[10];
    const float* b1     = (const float*)d_in[11];
    const float* w2     = (const float*)d_in[12];
    const float* b2     = (const float*)d_in[13];
    float* out = (float*)d_out;

    float *p_xw, *p_xn, *p_qkv, *p_att, *p_x1, *p_hid, *p_x2;
    unsigned *p_wh, *p_wl;
    cudaGetSymbolAddress((void**)&p_xw,  g_xw);
    cudaGetSymbolAddress((void**)&p_xn,  g_xn);
    cudaGetSymbolAddress((void**)&p_qkv, g_qkv);
    cudaGetSymbolAddress((void**)&p_att, g_att);
    cudaGetSymbolAddress((void**)&p_x1,  g_x1);
    cudaGetSymbolAddress((void**)&p_hid, g_hid);
    cudaGetSymbolAddress((void**)&p_x2,  g_x2);
    cudaGetSymbolAddress((void**)&p_wh,  g_wh);
    cudaGetSymbolAddress((void**)&p_wl,  g_wl);

    // 0. pre-split all weights to packed bf16x2 hi/lo
    k_wsplit<<<216, 256>>>(qkv_w, p_wh + WOFF_QKV, p_wl + WOFF_QKV, 192, 576);
    k_wsplit<<<72,  256>>>(proj_w, p_wh + WOFF_PROJ, p_wl + WOFF_PROJ, 192, 192);
    k_wsplit<<<288, 256>>>(w1, p_wh + WOFF_W1, p_wl + WOFF_W1, 192, 768);
    k_wsplit<<<288, 256>>>(w2, p_wh + WOFF_W2, p_wl + WOFF_W2, 768, 192);

    // 1. shift + partition + LN1  -> g_xw (shortcut), g_xn
    k_part_ln<<<4096, 256>>>(x, n1g, n1b);
    // 2. QKV GEMM: (T,192) @ (192,576)
    k_gemm_bf<0><<<dim3(9, T_ / 128), 256>>>(p_xn, p_wh + WOFF_QKV, p_wl + WOFF_QKV,
                                             qkv_b, nullptr, p_qkv, T_, 576, 192);
    // 3. windowed attention (tensor cores) -> g_att
    k_attn_tc<<<8192, 128>>>(rbt);
    // 4. proj GEMM + residual: x1 = xw + att @ proj_w + b
    k_gemm_bf<1><<<dim3(3, T_ / 128), 256>>>(p_att, p_wh + WOFF_PROJ, p_wl + WOFF_PROJ,
                                             proj_b, p_xw, p_x1, T_, 192, 192);
    // 5. LN2 -> g_xn (reuse)
    k_ln<<<T_ / 8, 256>>>(p_x1, n2g, n2b, p_xn);
    // 6. MLP1 GEMM + GELU: (T,192)@(192,768)
    k_gemm_bf<2><<<dim3(12, T_ / 128), 256>>>(p_xn, p_wh + WOFF_W1, p_wl + WOFF_W1,
                                              b1, nullptr, p_hid, T_, 768, 192);
    // 7. MLP2 GEMM + residual: x2 = x1 + hid @ w2 + b2
    k_gemm_bf<1><<<dim3(3, T_ / 128), 256>>>(p_hid, p_wh + WOFF_W2, p_wl + WOFF_W2,
                                             b2, p_x1, p_x2, T_, 192, 768);
    // 8. window reverse + roll -> out
    k_unpart<<<4096, 256>>>(out);
}